// round 7
// baseline (speedup 1.0000x reference)
#include <cuda_runtime.h>
#include <cstdint>
#include <math.h>

// IMDCT, symmetry-halved GEMM, round 7: 1-warp blocks, 8 z-rows/thread.
//
// z_col[j] = sum_f kr[j][f]*spec[b,f,col],  kr[j][f] = kernels[128+j][f]/(128*win[128+j])
//   out[b, s*256+k] = win[k]    *(k<128 ? -z_s[127-k]     : z_s[k-128])
//                   + win[k+256]*(k<128 ?  z_{s-1}[k+128] : z_{s-1}[383-k])
//
// Block = 32 threads (1 warp), NSEG=16 segments, 18 spec cols (s0-1..s0+16, zero-pad edges).
// Thread lane owns 8 z-rows t = lane+32m (m=0..7) x 9 col-pairs -> 72 independent
// fma.rn.f32x2 per f per warp; each 16B spec LDS broadcast feeds 16 FMA2.
// Weights: 2x float4 LDG per f (L2-hot), depth-1 prefetch.

#define NFREQ    256
#define TFRAMES  4096
#define NSEG     16
#define NCOLS    18
#define SSTR     20         // spec tile row stride (words); 80B keeps rows 16B-aligned
#define LOUT     1048832
#define DSTR     260        // Dt row stride (words); 1040B, 16B-aligned rows
#define SMBYTES  (NFREQ * SSTR * 4)   // 20,480 (Dt needs 18*260*4 = 18,720 <= this)

#define FMA2(acc, a, v) \
    asm("fma.rn.f32x2 %0, %1, %2, %0;" : "+l"(acc) : "l"(a), "l"(v))
#define PACK2(dst, x) \
    asm("mov.b64 %0, {%1, %1};" : "=l"(dst) : "r"(__float_as_uint(x)))

// Weights, reduced basis rows 128..383 mapped to t=0..255, pre-scaled by 1/(128*win):
//   g_w0[f*32+lane] = {kr(lane), kr(lane+32), kr(lane+64), kr(lane+96)}(f)      (m=0..3)
//   g_w1[f*32+lane] = {kr(lane+128), kr(lane+160), kr(lane+192), kr(lane+224)}  (m=4..7)
// One pad f-row each for depth-1 prefetch overrun.
__device__ float4 g_w0[257 * 32];
__device__ float4 g_w1[257 * 32];
__device__ float  g_win[512];

static __device__ __forceinline__ float win_of(int t) {
    return sinf((float)M_PI * (float)(2 * t + 1) * (1.0f / 1024.0f));
}

__global__ void prep_kernel(const float* __restrict__ kernels)
{
    int idx = blockIdx.x * blockDim.x + threadIdx.x;   // 8192 threads
    if (idx < 512) g_win[idx] = win_of(idx);
    int lane = idx & 31;
    int f    = idx >> 5;                               // 0..255
    const float s = 1.0f / 128.0f;
    float4 w0, w1;
    w0.x = s * kernels[(128 + lane      ) * 256 + f] / win_of(128 + lane      );
    w0.y = s * kernels[(128 + lane +  32) * 256 + f] / win_of(128 + lane +  32);
    w0.z = s * kernels[(128 + lane +  64) * 256 + f] / win_of(128 + lane +  64);
    w0.w = s * kernels[(128 + lane +  96) * 256 + f] / win_of(128 + lane +  96);
    w1.x = s * kernels[(128 + lane + 128) * 256 + f] / win_of(128 + lane + 128);
    w1.y = s * kernels[(128 + lane + 160) * 256 + f] / win_of(128 + lane + 160);
    w1.z = s * kernels[(128 + lane + 192) * 256 + f] / win_of(128 + lane + 192);
    w1.w = s * kernels[(128 + lane + 224) * 256 + f] / win_of(128 + lane + 224);
    g_w0[f * 32 + lane] = w0;
    g_w1[f * 32 + lane] = w1;
}

__global__ __launch_bounds__(32, 10)
void imdct_main_kernel(const float* __restrict__ spec, float* __restrict__ out)
{
    extern __shared__ float sm[];                      // spec tile, reused as Dt

    const int lane = threadIdx.x;                      // 0..31
    const int b    = blockIdx.y;
    const int s0   = blockIdx.x * NSEG;

    // ---- Stage spec cols c = s0-1 .. s0+16 (18 cols), zero-fill edges ----
    const float* specB = spec + (size_t)b * NFREQ * TFRAMES;
    #pragma unroll 4
    for (int idx = lane; idx < NFREQ * NCOLS; idx += 32) {
        int f = idx / NCOLS;
        int c = idx - f * NCOLS;
        int cg = s0 - 1 + c;
        float v = 0.0f;
        if (cg >= 0 && cg < TFRAMES)
            v = __ldg(&specB[(size_t)f * TFRAMES + cg]);
        sm[f * SSTR + c] = v;
    }
    __syncwarp();

    // ---- Accumulators: 8 rows x 9 col-pairs ----
    unsigned long long acc[8][9];
    #pragma unroll
    for (int m = 0; m < 8; m++)
        #pragma unroll
        for (int p = 0; p < 9; p++) acc[m][p] = 0ull;

    const uint32_t sbase = (uint32_t)__cvta_generic_to_shared(sm);
    const float4* __restrict__ w0p = g_w0 + lane;
    const float4* __restrict__ w1p = g_w1 + lane;

    float4 wc0 = w0p[0], wc1 = w1p[0];                 // depth-1 prefetch

    #pragma unroll 1
    for (int f = 0; f < NFREQ; f++) {
        float4 wn0 = w0p[(f + 1) * 32];
        float4 wn1 = w1p[(f + 1) * 32];

        unsigned long long w2[8];
        PACK2(w2[0], wc0.x); PACK2(w2[1], wc0.y); PACK2(w2[2], wc0.z); PACK2(w2[3], wc0.w);
        PACK2(w2[4], wc1.x); PACK2(w2[5], wc1.y); PACK2(w2[6], wc1.z); PACK2(w2[7], wc1.w);

        uint32_t srow = sbase + (uint32_t)(f * (SSTR * 4));
        #pragma unroll
        for (int q = 0; q < 4; q++) {
            unsigned long long v01, v23;               // cols (4q,4q+1), (4q+2,4q+3)
            asm volatile("ld.shared.v2.b64 {%0, %1}, [%2];"
                         : "=l"(v01), "=l"(v23) : "r"(srow + q * 16));
            #pragma unroll
            for (int m = 0; m < 8; m++) FMA2(acc[m][2*q],     w2[m], v01);
            #pragma unroll
            for (int m = 0; m < 8; m++) FMA2(acc[m][2*q + 1], w2[m], v23);
        }
        unsigned long long vt;                         // cols (16,17) -> pair 8
        asm volatile("ld.shared.b64 %0, [%1];" : "=l"(vt) : "r"(srow + 64));
        #pragma unroll
        for (int m = 0; m < 8; m++) FMA2(acc[m][8], w2[m], vt);

        wc0 = wn0; wc1 = wn1;
    }

    // ---- Stage Dt[c][j]: j = lane + 32m, c = 0..17 ----
    __syncwarp();                                      // done reading spec from sm
    #pragma unroll
    for (int m = 0; m < 8; m++) {
        int j = lane + 32 * m;
        #pragma unroll
        for (int p = 0; p < 9; p++) {
            unsigned long long a = acc[m][p];
            sm[(2 * p)     * DSTR + j] = __uint_as_float((unsigned)a);
            sm[(2 * p + 1) * DSTR + j] = __uint_as_float((unsigned)(a >> 32));
        }
    }
    __syncwarp();

    // ---- Windowed overlap-add epilogue: 2 passes of 128 k (4 consecutive k/thread) ----
    float* ob = out + (size_t)b * LOUT;
    #pragma unroll
    for (int pass = 0; pass < 2; pass++) {
        const int k0 = 4 * lane + 128 * pass;
        const bool lo = (pass == 0);
        float wA[4], wB[4];
        #pragma unroll
        for (int d = 0; d < 4; d++) {
            int k = k0 + d;
            wA[d] = __ldg(&g_win[k]) * (lo ? -1.0f : 1.0f);
            wB[d] = __ldg(&g_win[k + 256]);
        }
        const int aOff = lo ? (124 - k0) : (k0 - 128); // word offset of zA quad
        const int bOff = lo ? (k0 + 128) : (380 - k0); // word offset of zB quad

        #pragma unroll 4
        for (int i = 0; i < NSEG; i++) {
            int s = s0 + i;
            if (s <= 4096) {
                float4 a4 = *reinterpret_cast<const float4*>(sm + (i + 1) * DSTR + aOff);
                float4 b4 = *reinterpret_cast<const float4*>(sm + i * DSTR + bOff);
                float av[4], bv[4];
                if (lo) { av[0]=a4.w; av[1]=a4.z; av[2]=a4.y; av[3]=a4.x;
                          bv[0]=b4.x; bv[1]=b4.y; bv[2]=b4.z; bv[3]=b4.w; }
                else    { av[0]=a4.x; av[1]=a4.y; av[2]=a4.z; av[3]=a4.w;
                          bv[0]=b4.w; bv[1]=b4.z; bv[2]=b4.y; bv[3]=b4.x; }
                float4 o;
                o.x = wA[0] * av[0] + wB[0] * bv[0];
                o.y = wA[1] * av[1] + wB[1] * bv[1];
                o.z = wA[2] * av[2] + wB[2] * bv[2];
                o.w = wA[3] * av[3] + wB[3] * bv[3];
                *reinterpret_cast<float4*>(ob + (size_t)s * 256 + k0) = o;
            }
        }
    }
}

extern "C" void kernel_launch(void* const* d_in, const int* in_sizes, int n_in,
                              void* d_out, int out_size)
{
    const float* spec    = (const float*)d_in[0];   // [16,1,256,4096]
    const float* kernels = (const float*)d_in[1];   // [512,256]
    float* out = (float*)d_out;                     // [16,1048832]

    prep_kernel<<<32, 256>>>(kernels);              // 8192 threads

    cudaFuncSetAttribute(imdct_main_kernel,
                         cudaFuncAttributeMaxDynamicSharedMemorySize, SMBYTES);
    dim3 grid((4097 + NSEG - 1) / NSEG, 16);        // (257, 16)
    imdct_main_kernel<<<grid, 32, SMBYTES>>>(spec, out);
}

// round 8
// speedup vs baseline: 1.5226x; 1.5226x over previous
#include <cuda_runtime.h>
#include <cstdint>
#include <math.h>

// IMDCT, symmetry-halved GEMM, round 8: 4-warp blocks, 8 z-rows/lane, 14-seg windows.
//
// z_col[j] = sum_f kr[j][f]*spec[b,f,col],  kr[j][f] = kernels[128+j][f]/(128*win[128+j])
//   out[b, s*256+k] = win[k]    *(k<128 ? -z_s[127-k]     : z_s[k-128])
//                   + win[k+256]*(k<128 ?  z_{s-1}[k+128] : z_{s-1}[383-k])
//
// Block = 128 threads = 4 warps, NSEG=56 segments; shared spec tile of 58 cols
// (s0-1 .. s0+56, zero-padded edges). Warp w computes z for 16 cols [14w .. 14w+15]
// (8 packed pairs; 2-3 halo cols overlap, bit-identical). Lane owns 8 z-rows
// t = lane+32m -> each 8B spec broadcast feeds 8 FMA2. Weights: 2 LDG.128/lane/f,
// shared across the 4 warps via L1, depth-1 prefetch.

#define NFREQ    256
#define TFRAMES  4096
#define NSEG     56
#define NCOLS    58
#define SSTR     60         // spec tile row stride (words)
#define LOUT     1048832
#define DSTR     260        // Dt row stride (words)
#define SMBYTES  (NFREQ * SSTR * 4)   // 61,440 (Dt needs 58*260*4 = 60,320 <= this)

#define FMA2(acc, a, v) \
    asm("fma.rn.f32x2 %0, %1, %2, %0;" : "+l"(acc) : "l"(a), "l"(v))
#define PACK2(dst, x) \
    asm("mov.b64 %0, {%1, %1};" : "=l"(dst) : "r"(__float_as_uint(x)))

// Reduced-basis weights (rows 128..383 -> t=0..255), pre-scaled by 1/(128*win):
//   g_w0[f*32+lane] = {kr(lane), kr(lane+32), kr(lane+64), kr(lane+96)}(f)
//   g_w1[f*32+lane] = {kr(lane+128), kr(lane+160), kr(lane+192), kr(lane+224)}(f)
// One pad f-row each for depth-1 prefetch overrun.
__device__ float4 g_w0[257 * 32];
__device__ float4 g_w1[257 * 32];
__device__ float  g_win[512];

static __device__ __forceinline__ float win_of(int t) {
    return sinf((float)M_PI * (float)(2 * t + 1) * (1.0f / 1024.0f));
}

__global__ void prep_kernel(const float* __restrict__ kernels)
{
    int idx = blockIdx.x * blockDim.x + threadIdx.x;   // 8192 threads
    if (idx < 512) g_win[idx] = win_of(idx);
    int lane = idx & 31;
    int f    = idx >> 5;                               // 0..255
    const float s = 1.0f / 128.0f;
    float4 w0, w1;
    w0.x = s * kernels[(128 + lane      ) * 256 + f] / win_of(128 + lane      );
    w0.y = s * kernels[(128 + lane +  32) * 256 + f] / win_of(128 + lane +  32);
    w0.z = s * kernels[(128 + lane +  64) * 256 + f] / win_of(128 + lane +  64);
    w0.w = s * kernels[(128 + lane +  96) * 256 + f] / win_of(128 + lane +  96);
    w1.x = s * kernels[(128 + lane + 128) * 256 + f] / win_of(128 + lane + 128);
    w1.y = s * kernels[(128 + lane + 160) * 256 + f] / win_of(128 + lane + 160);
    w1.z = s * kernels[(128 + lane + 192) * 256 + f] / win_of(128 + lane + 192);
    w1.w = s * kernels[(128 + lane + 224) * 256 + f] / win_of(128 + lane + 224);
    g_w0[f * 32 + lane] = w0;
    g_w1[f * 32 + lane] = w1;
}

__global__ __launch_bounds__(128, 3)
void imdct_main_kernel(const float* __restrict__ spec, float* __restrict__ out)
{
    extern __shared__ float sm[];                      // spec tile, reused as Dt

    const int tid  = threadIdx.x;                      // 0..127
    const int lane = tid & 31;
    const int w    = tid >> 5;                         // warp 0..3 -> col window 14w
    const int b    = blockIdx.y;
    const int s0   = blockIdx.x * NSEG;

    // ---- Stage spec cols c = s0-1 .. s0+56 (58 cols), zero-fill edges/pad ----
    const float* specB = spec + (size_t)b * NFREQ * TFRAMES;
    #pragma unroll 4
    for (int idx = tid; idx < NFREQ * SSTR; idx += 128) {
        int f = idx / SSTR;
        int j = idx - f * SSTR;
        int c = s0 - 1 + j;
        float v = 0.0f;
        if (j < NCOLS && c >= 0 && c < TFRAMES)
            v = __ldg(&specB[(size_t)f * TFRAMES + c]);
        sm[idx] = v;
    }
    __syncthreads();

    // ---- Accumulators: 8 rows x 8 col-pairs (window cols 14w .. 14w+15) ----
    unsigned long long acc[8][8];
    #pragma unroll
    for (int m = 0; m < 8; m++)
        #pragma unroll
        for (int p = 0; p < 8; p++) acc[m][p] = 0ull;

    const uint32_t sbase = (uint32_t)__cvta_generic_to_shared(sm) + (uint32_t)(14 * w * 4);
    const float4* __restrict__ w0p = g_w0 + lane;
    const float4* __restrict__ w1p = g_w1 + lane;

    float4 wc0 = w0p[0], wc1 = w1p[0];                 // depth-1 prefetch

    #pragma unroll 1
    for (int f = 0; f < NFREQ; f++) {
        float4 wn0 = w0p[(f + 1) * 32];
        float4 wn1 = w1p[(f + 1) * 32];

        unsigned long long w2[8];
        PACK2(w2[0], wc0.x); PACK2(w2[1], wc0.y); PACK2(w2[2], wc0.z); PACK2(w2[3], wc0.w);
        PACK2(w2[4], wc1.x); PACK2(w2[5], wc1.y); PACK2(w2[6], wc1.z); PACK2(w2[7], wc1.w);

        uint32_t srow = sbase + (uint32_t)(f * (SSTR * 4));
        #pragma unroll
        for (int p = 0; p < 8; p++) {                  // 8B broadcast: window cols (2p, 2p+1)
            unsigned long long v;
            asm volatile("ld.shared.b64 %0, [%1];" : "=l"(v) : "r"(srow + p * 8));
            #pragma unroll
            for (int m = 0; m < 8; m++) FMA2(acc[m][p], w2[m], v);
        }

        wc0 = wn0; wc1 = wn1;
    }

    // ---- Stage Dt[col][j]: warp w stores window cols 14w+2p (+1), j = lane+32m ----
    __syncthreads();                                   // done reading spec from sm
    #pragma unroll
    for (int m = 0; m < 8; m++) {
        int j = lane + 32 * m;
        #pragma unroll
        for (int p = 0; p < 8; p++) {
            unsigned long long a = acc[m][p];
            sm[(14 * w + 2 * p)     * DSTR + j] = __uint_as_float((unsigned)a);
            sm[(14 * w + 2 * p + 1) * DSTR + j] = __uint_as_float((unsigned)(a >> 32));
        }
    }
    __syncthreads();

    // ---- Windowed overlap-add epilogue: 4 consecutive k/thread, 28 segs/thread ----
    {
        const int lt = tid & 63;
        const int h  = tid >> 6;                       // segment half
        const int k0 = 4 * lt;                         // 0..252
        const bool lo = (lt < 32);                     // warp-uniform
        float wA[4], wB[4];
        #pragma unroll
        for (int d = 0; d < 4; d++) {
            int k = k0 + d;
            wA[d] = __ldg(&g_win[k]) * (lo ? -1.0f : 1.0f);
            wB[d] = __ldg(&g_win[k + 256]);
        }
        const int aOff = lo ? (124 - k0) : (k0 - 128); // word offset of zA quad
        const int bOff = lo ? (k0 + 128) : (380 - k0); // word offset of zB quad
        float* ob = out + (size_t)b * LOUT + k0;

        #pragma unroll 4
        for (int i = 0; i < NSEG / 2; i++) {
            int ci = 28 * h + i;                       // zB col; zA col = ci+1
            int s  = s0 + ci;
            if (s <= 4096) {
                float4 a4 = *reinterpret_cast<const float4*>(sm + (ci + 1) * DSTR + aOff);
                float4 b4 = *reinterpret_cast<const float4*>(sm + ci * DSTR + bOff);
                float av[4], bv[4];
                if (lo) { av[0]=a4.w; av[1]=a4.z; av[2]=a4.y; av[3]=a4.x;
                          bv[0]=b4.x; bv[1]=b4.y; bv[2]=b4.z; bv[3]=b4.w; }
                else    { av[0]=a4.x; av[1]=a4.y; av[2]=a4.z; av[3]=a4.w;
                          bv[0]=b4.w; bv[1]=b4.z; bv[2]=b4.y; bv[3]=b4.x; }
                float4 o;
                o.x = wA[0] * av[0] + wB[0] * bv[0];
                o.y = wA[1] * av[1] + wB[1] * bv[1];
                o.z = wA[2] * av[2] + wB[2] * bv[2];
                o.w = wA[3] * av[3] + wB[3] * bv[3];
                *reinterpret_cast<float4*>(ob + (size_t)s * 256) = o;
            }
        }
    }
}

extern "C" void kernel_launch(void* const* d_in, const int* in_sizes, int n_in,
                              void* d_out, int out_size)
{
    const float* spec    = (const float*)d_in[0];   // [16,1,256,4096]
    const float* kernels = (const float*)d_in[1];   // [512,256]
    float* out = (float*)d_out;                     // [16,1048832]

    prep_kernel<<<32, 256>>>(kernels);              // 8192 threads

    cudaFuncSetAttribute(imdct_main_kernel,
                         cudaFuncAttributeMaxDynamicSharedMemorySize, SMBYTES);
    dim3 grid((4097 + NSEG - 1) / NSEG, 16);        // (74, 16)
    imdct_main_kernel<<<grid, 128, SMBYTES>>>(spec, out);
}